// round 14
// baseline (speedup 1.0000x reference)
#include <cuda_runtime.h>
#include <cuda_fp16.h>
#include <math.h>

#define N_ATOMS 10000
#define N_EDGES 320000
// K = [128, 96, 64, 32], n_max = [8,6,4,2]
// A/B feature layout (960): l0 [0,128) | l1 [128,416) m-major | l2 [416,736) | l3 [736,960)
#define FV 960
#define FP 320   // fpre per atom: B0(128) + inv(192)

// ---------------- scratch (static device memory; no allocations) -------------
// g_deg/g_fill start zeroed (BSS) and are re-zeroed at the end of k_reduce.
__device__ float  g_geo[N_EDGES * 24];     // per edge: R[8], Y1..Y15, species(sender) bits
__device__ int    g_deg[N_ATOMS];
__device__ int    g_fill[N_ATOMS];
__device__ int    g_off[N_ATOMS + 1];
__device__ int    g_csr[N_EDGES];
__device__ __half g_Aemb[(size_t)N_ATOMS * FV];   // fp16: halves phase-B gather bytes
__device__ float  g_fpre[(size_t)N_ATOMS * FP];
__device__ float  g_eatom[N_ATOMS];

// ---------------- kernel 1: per-edge geometry + degree count -----------------
__global__ void k_geom(const float* __restrict__ pos, const int* __restrict__ species,
                       const int* __restrict__ snd, const int* __restrict__ rcv) {
    int e = blockIdx.x * blockDim.x + threadIdx.x;
    if (e >= N_EDGES) return;
    int si = snd[e], ri = rcv[e];
    float dx = pos[ri * 3 + 0] - pos[si * 3 + 0];
    float dy = pos[ri * 3 + 1] - pos[si * 3 + 1];
    float dz = pos[ri * 3 + 2] - pos[si * 3 + 2];
    float r = sqrtf(dx * dx + dy * dy + dz * dz + 1e-12f);
    float inv = 1.0f / r;
    float x = dx * inv, y = dy * inv, z = dz * inv;
    float fc = (r < 5.0f) ? 0.5f * (cosf(3.14159265358979f * r * 0.2f) + 1.0f) : 0.0f;

    float R[8];
    #pragma unroll
    for (int b = 0; b < 8; b++) {
        float mu = (5.0f / 7.0f) * (float)b;
        float d2 = r - mu;
        R[b] = expf(-d2 * d2) * fc;
    }
    const float s3  = 1.7320508075688772f;
    const float c33 = 0.7905694150420949f;
    const float c31 = 0.6123724356957945f;
    const float s15 = 3.872983346207417f;

    float4* g4 = (float4*)(g_geo + (size_t)e * 24);
    g4[0] = make_float4(R[0], R[1], R[2], R[3]);
    g4[1] = make_float4(R[4], R[5], R[6], R[7]);
    g4[2] = make_float4(x, y, z, s3 * x * y);
    g4[3] = make_float4(s3 * y * z, 0.5f * (3.0f * z * z - 1.0f), s3 * x * z,
                        0.5f * s3 * (x * x - y * y));
    g4[4] = make_float4(c33 * y * (3.0f * x * x - y * y), s15 * x * y * z,
                        c31 * y * (5.0f * z * z - 1.0f), 0.5f * z * (5.0f * z * z - 3.0f));
    g4[5] = make_float4(c31 * x * (5.0f * z * z - 1.0f), 0.5f * s15 * (x * x - y * y) * z,
                        c33 * x * (x * x - 3.0f * y * y), __int_as_float(species[si]));
    atomicAdd(&g_deg[ri], 1);
}

// ---------------- kernel 2: exclusive scan of degrees ------------------------
__global__ void k_scan() {
    __shared__ int sh[1024];
    int t = threadIdx.x;
    const int CH = 10;
    int base = t * CH;
    int loc[CH];
    int s = 0;
    #pragma unroll
    for (int j = 0; j < CH; j++) {
        int idx = base + j;
        int v = (idx < N_ATOMS) ? g_deg[idx] : 0;
        loc[j] = v; s += v;
    }
    sh[t] = s;
    __syncthreads();
    for (int o = 1; o < 1024; o <<= 1) {
        int v = (t >= o) ? sh[t - o] : 0;
        __syncthreads();
        sh[t] += v;
        __syncthreads();
    }
    int ex = sh[t] - s;
    #pragma unroll
    for (int j = 0; j < CH; j++) {
        int idx = base + j;
        if (idx < N_ATOMS) { g_off[idx] = ex; ex += loc[j]; }
    }
    if (t == 1023) g_off[N_ATOMS] = sh[1023];
}

// ---------------- kernel 3: CSR fill ------------------------------------------
__global__ void k_fill(const int* __restrict__ rcv) {
    int e = blockIdx.x * blockDim.x + threadIdx.x;
    if (e >= N_EDGES) return;
    int r = rcv[e];
    int p = g_off[r] + atomicAdd(&g_fill[r], 1);
    g_csr[p] = e;
}

// ---------------- kernel 4: phase A gather (one block per atom) --------------
// b-axis-contiguous layouts: wr transposed to [k][b], T to [s][lm*8+b],
// E1 to [c][lm*8+b] so E1-build and the output contraction use LDS.128.
__global__ void __launch_bounds__(128) k_phaseA(
    const float* __restrict__ emb,
    const float* __restrict__ Wr0, const float* __restrict__ Wr1,
    const float* __restrict__ Wr2, const float* __restrict__ Wr3,
    const int* __restrict__ species) {
    __shared__ float4 wr4[640];       // 2560 floats, transposed [k][b]
    __shared__ float  em[64];
    __shared__ float4 T4[128];        // 512 floats: T[s][lm*8+b]
    __shared__ float4 E1_4[512];      // 2048 floats: E1[c][lm*8+b]
    __shared__ float  sg[16 * 24];
    __shared__ int    es[16];

    float* wr = (float*)wr4;
    float* T  = (float*)T4;

    int t = threadIdx.x;
    int i = blockIdx.x;

    // transposed weight load: wr[woff + k*8 + b] = Wr_l[b*Kl + k]
    for (int j = t; j < 1024; j += 128) {
        int b = j >> 7, k = j & 127;
        wr[(k << 3) + b] = Wr0[j];
    }
    for (int j = t; j < 768; j += 128) {
        int b = j / 96, k = j - b * 96;
        wr[1024 + k * 8 + b] = Wr1[j];
    }
    for (int j = t; j < 512; j += 128) {
        int b = j >> 6, k = j & 63;
        wr[1792 + (k << 3) + b] = Wr2[j];
    }
    for (int j = t; j < 256; j += 128) {
        int b = j >> 5, k = j & 31;
        wr[2304 + (k << 3) + b] = Wr3[j];
    }
    if (t < 64) em[t] = emb[t];

    int b = t >> 4, lm = t & 15;
    float a0 = 0.f, a1 = 0.f, a2 = 0.f, a3 = 0.f;
    int start = g_off[i];
    int deg = g_off[i + 1] - start;
    __syncthreads();

    for (int c0 = 0; c0 < deg; c0 += 16) {
        int nn = min(16, deg - c0);
        if (t < nn) es[t] = g_csr[start + c0 + t];
        __syncthreads();
        for (int j = t; j < nn * 24; j += 128) {
            int ec = j / 24, w = j - ec * 24;
            sg[ec * 24 + w] = g_geo[(size_t)es[ec] * 24 + w];
        }
        __syncthreads();
        for (int ec = 0; ec < nn; ec++) {
            float R  = sg[ec * 24 + b];
            float Yv = (lm == 0) ? 1.0f : sg[ec * 24 + 7 + lm];
            int sp = __float_as_int(sg[ec * 24 + 23]);
            float v = R * Yv;
            if      (sp == 0) a0 += v;
            else if (sp == 1) a1 += v;
            else if (sp == 2) a2 += v;
            else              a3 += v;
        }
        __syncthreads();
    }
    {
        int tl = (lm << 3) + b;        // transposed slot
        T[tl]        = a0;
        T[128 + tl]  = a1;
        T[256 + tl]  = a2;
        T[384 + tl]  = a3;
    }
    __syncthreads();

    // E1[c][lm*8+b] = sum_s em[s*16+c] * T[s][lm*8+b]   (float4 over b-axis)
    for (int j4 = t; j4 < 512; j4 += 128) {
        int c = j4 >> 5, r4 = j4 & 31;
        float4 t0 = T4[r4], t1 = T4[32 + r4], t2 = T4[64 + r4], t3 = T4[96 + r4];
        float e0 = em[c], e1 = em[16 + c], e2 = em[32 + c], e3 = em[48 + c];
        float4 o;
        o.x = e0 * t0.x + e1 * t1.x + e2 * t2.x + e3 * t3.x;
        o.y = e0 * t0.y + e1 * t1.y + e2 * t2.y + e3 * t3.y;
        o.z = e0 * t0.z + e1 * t1.z + e2 * t2.z + e3 * t3.z;
        o.w = e0 * t0.w + e1 * t1.w + e2 * t2.w + e3 * t3.w;
        E1_4[j4] = o;
    }
    __syncthreads();

    int spi = species[i];
    __half* out = g_Aemb + (size_t)i * FV;
    for (int kp = t; kp < FV; kp += 128) {
        int k, nmax, lmb, woff;
        if (kp < 128)      { k = kp;                          nmax = 8; lmb = 0;     woff = 0;    }
        else if (kp < 416) { int u = kp - 128; int m = u / 96; k = u - 96 * m; nmax = 6; lmb = 1 + m; woff = 1024; }
        else if (kp < 736) { int u = kp - 416; int m = u >> 6; k = u & 63;     nmax = 4; lmb = 4 + m; woff = 1792; }
        else               { int u = kp - 736; int m = u >> 5; k = u & 31;     nmax = 2; lmb = 9 + m; woff = 2304; }
        int c = k / nmax;
        const float4* e4 = &E1_4[(c << 5) + (lmb << 1)];           // c*128 + lmb*8 floats
        const float4* w4 = &wr4[(woff >> 2) + (k << 1)];           // woff + k*8 floats
        float4 ea = e4[0], eb = e4[1];
        float4 wa = w4[0], wb = w4[1];
        float v = ea.x * wa.x + ea.y * wa.y + ea.z * wa.z + ea.w * wa.w
                + eb.x * wb.x + eb.y * wb.y + eb.z * wb.z + eb.w * wb.w;
        out[kp] = __float2half(0.1f * em[spi * 16 + c] * v);
    }
}

// ---------------- kernel 5: phase B gather (one block per atom, 320 thr) -----
// Re staged as float4 pairs; inner loop reads 2x LDS.128 broadcast per edge
// instead of 8 scalar LDS. Tile 32 + unroll 4 preserved from the 420us config.
__global__ void __launch_bounds__(320) k_phaseB(
    const float* __restrict__ Vr0, const float* __restrict__ Vr1,
    const float* __restrict__ Vr2, const float* __restrict__ Vr3,
    const int* __restrict__ snd) {
    __shared__ int    se[32];
    __shared__ int    ee[32];
    __shared__ float4 Re4[32 * 2];
    __shared__ float  Bsh[FV];
    __shared__ float  invsh[192];

    int t = threadIdx.x;
    int i = blockIdx.x;

    int lvl, k, base;
    const float* Vp; int Kl;
    if (t < 128)      { lvl = 0; k = t;       base = k;       Vp = Vr0; Kl = 128; }
    else if (t < 224) { lvl = 1; k = t - 128; base = 128 + k; Vp = Vr1; Kl = 96;  }
    else if (t < 288) { lvl = 2; k = t - 224; base = 416 + k; Vp = Vr2; Kl = 64;  }
    else              { lvl = 3; k = t - 288; base = 736 + k; Vp = Vr3; Kl = 32;  }
    float v0 = Vp[0 * Kl + k], v1 = Vp[1 * Kl + k], v2 = Vp[2 * Kl + k], v3 = Vp[3 * Kl + k];
    float v4 = Vp[4 * Kl + k], v5 = Vp[5 * Kl + k], v6 = Vp[6 * Kl + k], v7 = Vp[7 * Kl + k];

    float a0 = 0.f, a1 = 0.f, a2 = 0.f, a3 = 0.f, a4 = 0.f, a5 = 0.f, a6 = 0.f;

    int start = g_off[i];
    int deg = g_off[i + 1] - start;

    for (int c0 = 0; c0 < deg; c0 += 32) {
        int nn = min(32, deg - c0);
        if (t < nn) {
            int e = g_csr[start + c0 + t];
            ee[t] = e;
            se[t] = snd[e];
        }
        __syncthreads();
        // stage R[8] per edge as two float4s (64 float4s total)
        for (int j = t; j < nn * 2; j += 320) {
            int ec = j >> 1, h = j & 1;
            Re4[(ec << 1) + h] = ((const float4*)(g_geo + (size_t)ee[ec] * 24))[h];
        }
        __syncthreads();

        if (lvl == 0) {
            #pragma unroll 4
            for (int ec = 0; ec < nn; ec++) {
                const __half* ar = g_Aemb + (size_t)se[ec] * FV;
                float4 ra = Re4[ec * 2], rb = Re4[ec * 2 + 1];
                float vl = ra.x*v0 + ra.y*v1 + ra.z*v2 + ra.w*v3
                         + rb.x*v4 + rb.y*v5 + rb.z*v6 + rb.w*v7;
                a0 += __half2float(ar[base]) * vl;
            }
        } else if (lvl == 1) {
            #pragma unroll 4
            for (int ec = 0; ec < nn; ec++) {
                const __half* ar = g_Aemb + (size_t)se[ec] * FV;
                float4 ra = Re4[ec * 2], rb = Re4[ec * 2 + 1];
                float vl = ra.x*v0 + ra.y*v1 + ra.z*v2 + ra.w*v3
                         + rb.x*v4 + rb.y*v5 + rb.z*v6 + rb.w*v7;
                a0 += __half2float(ar[base])       * vl;
                a1 += __half2float(ar[base + 96])  * vl;
                a2 += __half2float(ar[base + 192]) * vl;
            }
        } else if (lvl == 2) {
            #pragma unroll 4
            for (int ec = 0; ec < nn; ec++) {
                const __half* ar = g_Aemb + (size_t)se[ec] * FV;
                float4 ra = Re4[ec * 2], rb = Re4[ec * 2 + 1];
                float vl = ra.x*v0 + ra.y*v1 + ra.z*v2 + ra.w*v3
                         + rb.x*v4 + rb.y*v5 + rb.z*v6 + rb.w*v7;
                a0 += __half2float(ar[base])       * vl;
                a1 += __half2float(ar[base + 64])  * vl;
                a2 += __half2float(ar[base + 128]) * vl;
                a3 += __half2float(ar[base + 192]) * vl;
                a4 += __half2float(ar[base + 256]) * vl;
            }
        } else {
            #pragma unroll 4
            for (int ec = 0; ec < nn; ec++) {
                const __half* ar = g_Aemb + (size_t)se[ec] * FV;
                float4 ra = Re4[ec * 2], rb = Re4[ec * 2 + 1];
                float vl = ra.x*v0 + ra.y*v1 + ra.z*v2 + ra.w*v3
                         + rb.x*v4 + rb.y*v5 + rb.z*v6 + rb.w*v7;
                a0 += __half2float(ar[base])       * vl;
                a1 += __half2float(ar[base + 32])  * vl;
                a2 += __half2float(ar[base + 64])  * vl;
                a3 += __half2float(ar[base + 96])  * vl;
                a4 += __half2float(ar[base + 128]) * vl;
                a5 += __half2float(ar[base + 160]) * vl;
                a6 += __half2float(ar[base + 192]) * vl;
            }
        }
        __syncthreads();
    }

    if (lvl == 0) {
        Bsh[base] = 0.1f * a0;
    } else if (lvl == 1) {
        Bsh[base] = 0.1f * a0; Bsh[base + 96] = 0.1f * a1; Bsh[base + 192] = 0.1f * a2;
    } else if (lvl == 2) {
        Bsh[base] = 0.1f * a0; Bsh[base + 64] = 0.1f * a1; Bsh[base + 128] = 0.1f * a2;
        Bsh[base + 192] = 0.1f * a3; Bsh[base + 256] = 0.1f * a4;
    } else {
        Bsh[base] = 0.1f * a0; Bsh[base + 32] = 0.1f * a1; Bsh[base + 64] = 0.1f * a2;
        Bsh[base + 96] = 0.1f * a3; Bsh[base + 128] = 0.1f * a4;
        Bsh[base + 160] = 0.1f * a5; Bsh[base + 192] = 0.1f * a6;
    }
    __syncthreads();

    if (t < 192) {
        int off, KK, cnt, kk;
        float norm;
        if (t < 96)       { off = 128; KK = 96; cnt = 3; kk = t;       norm = 0.5773502691896258f; }
        else if (t < 160) { off = 416; KK = 64; cnt = 5; kk = t - 96;  norm = 0.4472135954999579f; }
        else              { off = 736; KK = 32; cnt = 7; kk = t - 160; norm = 0.3779644730092272f; }
        float s = 0.f;
        for (int m = 0; m < cnt; m++) { float v = Bsh[off + m * KK + kk]; s += v * v; }
        invsh[t] = s * norm;
    }
    __syncthreads();

    g_fpre[(size_t)i * FP + t] = (t < 128) ? Bsh[t] : invsh[t - 128];
}

// ---------------- kernel 6: tail (inv@N + MLP), 16 atoms / block -------------
__global__ void __launch_bounds__(256) k_tail(
    const float* __restrict__ N1, const float* __restrict__ N2,
    const float* __restrict__ N3,
    const float* __restrict__ W1, const float* __restrict__ W2,
    const float* __restrict__ w_out, const float* __restrict__ comp,
    const int* __restrict__ species) {
    __shared__ float fin[16 * FP];     // 20 KB
    __shared__ float f2sh[16 * 128];   // 8 KB (reused for stage-3 partials)
    __shared__ float h1sh[16 * 128];   // 8 KB

    int t = threadIdx.x;
    int blk = blockIdx.x;
    int c = t & 127;
    int g = t >> 7;
    int abase = g * 8;

    for (int j = t; j < 16 * FP; j += 256)
        fin[j] = g_fpre[(size_t)blk * 16 * FP + j];
    __syncthreads();

    float acc[8];
    #pragma unroll
    for (int a = 0; a < 8; a++) acc[a] = fin[(abase + a) * FP + c];
    for (int j = 0; j < 96; j++) {
        float nv = N1[j * 128 + c];
        #pragma unroll
        for (int a = 0; a < 8; a++) acc[a] += fin[(abase + a) * FP + 128 + j] * nv;
    }
    for (int j = 0; j < 64; j++) {
        float nv = N2[j * 128 + c];
        #pragma unroll
        for (int a = 0; a < 8; a++) acc[a] += fin[(abase + a) * FP + 224 + j] * nv;
    }
    for (int j = 0; j < 32; j++) {
        float nv = N3[j * 128 + c];
        #pragma unroll
        for (int a = 0; a < 8; a++) acc[a] += fin[(abase + a) * FP + 288 + j] * nv;
    }
    #pragma unroll
    for (int a = 0; a < 8; a++) f2sh[(abase + a) * 128 + c] = acc[a];
    __syncthreads();

    float acc2[8];
    #pragma unroll
    for (int a = 0; a < 8; a++) acc2[a] = 0.f;
    for (int kk = 0; kk < 128; kk++) {
        float w = W1[kk * 128 + c];
        #pragma unroll
        for (int a = 0; a < 8; a++) acc2[a] += f2sh[(abase + a) * 128 + kk] * w;
    }
    #pragma unroll
    for (int a = 0; a < 8; a++) {
        float s = acc2[a];
        h1sh[(abase + a) * 128 + c] = s / (1.0f + expf(-s));
    }
    __syncthreads();

    float acc3[8];
    #pragma unroll
    for (int a = 0; a < 8; a++) acc3[a] = 0.f;
    for (int kk = 0; kk < 128; kk++) {
        float w = W2[kk * 128 + c];
        #pragma unroll
        for (int a = 0; a < 8; a++) acc3[a] += h1sh[(abase + a) * 128 + kk] * w;
    }
    float wo = w_out[c];
    __syncthreads();
    #pragma unroll
    for (int a = 0; a < 8; a++) f2sh[(abase + a) * 128 + c] = acc3[a] * wo;
    __syncthreads();

    if (t < 16) {
        float s = 0.f;
        for (int j = 0; j < 128; j++) s += f2sh[t * 128 + j];
        int idx = blk * 16 + t;
        g_eatom[idx] = s + comp[species[idx]];
    }
}

// ---------------- kernel 7: final reduction + counter reset ------------------
__global__ void k_reduce(float* __restrict__ out) {
    __shared__ double sh[1024];
    int t = threadIdx.x;
    double s = 0.0;
    for (int i = t; i < N_ATOMS; i += 1024) s += (double)g_eatom[i];
    sh[t] = s;
    __syncthreads();
    for (int o = 512; o > 0; o >>= 1) {
        if (t < o) sh[t] += sh[t + o];
        __syncthreads();
    }
    if (t == 0) out[0] = (float)sh[0];
    for (int i = t; i < N_ATOMS; i += 1024) { g_deg[i] = 0; g_fill[i] = 0; }
}

// ---------------- launch ------------------------------------------------------
extern "C" void kernel_launch(void* const* d_in, const int* in_sizes, int n_in,
                              void* d_out, int out_size) {
    const float *pos = 0, *emb = 0, *Wr0 = 0, *Wr1 = 0, *Wr2 = 0, *Wr3 = 0;
    const float *Vr0 = 0, *Vr1 = 0, *Vr2 = 0, *Vr3 = 0;
    const float *N1 = 0, *N2 = 0, *N3 = 0, *W1 = 0, *W2 = 0, *w_out = 0, *comp = 0;
    const int *species = 0, *snd = 0, *rcv = 0;

    for (int i = 0; i < n_in; i++) {
        int s = in_sizes[i];
        const void* p = d_in[i];
        switch (s) {
            case 30000:  pos = (const float*)p; break;
            case 64:     emb = (const float*)p; break;
            case 10000:  species = (const int*)p; break;
            case 320000: if (!snd) snd = (const int*)p; else rcv = (const int*)p; break;
            case 1024:   if (!Wr0) Wr0 = (const float*)p; else Vr0 = (const float*)p; break;
            case 768:    if (!Wr1) Wr1 = (const float*)p; else Vr1 = (const float*)p; break;
            case 512:    if (!Wr2) Wr2 = (const float*)p; else Vr2 = (const float*)p; break;
            case 256:    if (!Wr3) Wr3 = (const float*)p; else Vr3 = (const float*)p; break;
            case 12288:  N1 = (const float*)p; break;  // M1 then N1: keep LAST
            case 8192:   N2 = (const float*)p; break;  // M2 then N2: keep LAST
            case 4096:   N3 = (const float*)p; break;  // M3 then N3: keep LAST
            case 16384:  if (!W1) W1 = (const float*)p; else W2 = (const float*)p; break;
            case 128:    w_out = (const float*)p; break;
            case 4:      comp = (const float*)p; break;
            default: break;
        }
    }

    float* out = (float*)d_out;

    k_geom<<<(N_EDGES + 255) / 256, 256>>>(pos, species, snd, rcv);
    k_scan<<<1, 1024>>>();
    k_fill<<<(N_EDGES + 255) / 256, 256>>>(rcv);
    k_phaseA<<<N_ATOMS, 128>>>(emb, Wr0, Wr1, Wr2, Wr3, species);
    k_phaseB<<<N_ATOMS, 320>>>(Vr0, Vr1, Vr2, Vr3, snd);
    k_tail<<<N_ATOMS / 16, 256>>>(N1, N2, N3, W1, W2, w_out, comp, species);
    k_reduce<<<1, 1024>>>(out);
}

// round 15
// speedup vs baseline: 1.0050x; 1.0050x over previous
#include <cuda_runtime.h>
#include <cuda_fp16.h>
#include <math.h>

#define N_ATOMS 10000
#define N_EDGES 320000
// K = [128, 96, 64, 32], n_max = [8,6,4,2]
// A/B feature layout (960): l0 [0,128) | l1 [128,416) m-major | l2 [416,736) | l3 [736,960)
#define FV 960
#define FP 320   // fpre per atom: B0(128) + inv(192)

// ---------------- scratch (static device memory; no allocations) -------------
// g_deg/g_fill start zeroed (BSS) and are re-zeroed at the end of k_reduce.
__device__ float  g_geo[N_EDGES * 24];     // per edge: R[8], Y1..Y15, species(sender) bits
__device__ int    g_deg[N_ATOMS];
__device__ int    g_fill[N_ATOMS];
__device__ int    g_off[N_ATOMS + 1];
__device__ int    g_csr[N_EDGES];
__device__ __half g_Aemb[(size_t)N_ATOMS * FV];   // fp16: halves phase-B gather bytes
__device__ float  g_fpre[(size_t)N_ATOMS * FP];
__device__ float  g_eatom[N_ATOMS];

// ---------------- kernel 1: per-edge geometry + degree count -----------------
__global__ void k_geom(const float* __restrict__ pos, const int* __restrict__ species,
                       const int* __restrict__ snd, const int* __restrict__ rcv) {
    int e = blockIdx.x * blockDim.x + threadIdx.x;
    if (e >= N_EDGES) return;
    int si = snd[e], ri = rcv[e];
    float dx = pos[ri * 3 + 0] - pos[si * 3 + 0];
    float dy = pos[ri * 3 + 1] - pos[si * 3 + 1];
    float dz = pos[ri * 3 + 2] - pos[si * 3 + 2];
    float r = sqrtf(dx * dx + dy * dy + dz * dz + 1e-12f);
    float inv = 1.0f / r;
    float x = dx * inv, y = dy * inv, z = dz * inv;
    float fc = (r < 5.0f) ? 0.5f * (cosf(3.14159265358979f * r * 0.2f) + 1.0f) : 0.0f;

    float R[8];
    #pragma unroll
    for (int b = 0; b < 8; b++) {
        float mu = (5.0f / 7.0f) * (float)b;
        float d2 = r - mu;
        R[b] = expf(-d2 * d2) * fc;
    }
    const float s3  = 1.7320508075688772f;
    const float c33 = 0.7905694150420949f;
    const float c31 = 0.6123724356957945f;
    const float s15 = 3.872983346207417f;

    float4* g4 = (float4*)(g_geo + (size_t)e * 24);
    g4[0] = make_float4(R[0], R[1], R[2], R[3]);
    g4[1] = make_float4(R[4], R[5], R[6], R[7]);
    g4[2] = make_float4(x, y, z, s3 * x * y);
    g4[3] = make_float4(s3 * y * z, 0.5f * (3.0f * z * z - 1.0f), s3 * x * z,
                        0.5f * s3 * (x * x - y * y));
    g4[4] = make_float4(c33 * y * (3.0f * x * x - y * y), s15 * x * y * z,
                        c31 * y * (5.0f * z * z - 1.0f), 0.5f * z * (5.0f * z * z - 3.0f));
    g4[5] = make_float4(c31 * x * (5.0f * z * z - 1.0f), 0.5f * s15 * (x * x - y * y) * z,
                        c33 * x * (x * x - 3.0f * y * y), __int_as_float(species[si]));
    atomicAdd(&g_deg[ri], 1);
}

// ---------------- kernel 2: exclusive scan of degrees ------------------------
__global__ void k_scan() {
    __shared__ int sh[1024];
    int t = threadIdx.x;
    const int CH = 10;
    int base = t * CH;
    int loc[CH];
    int s = 0;
    #pragma unroll
    for (int j = 0; j < CH; j++) {
        int idx = base + j;
        int v = (idx < N_ATOMS) ? g_deg[idx] : 0;
        loc[j] = v; s += v;
    }
    sh[t] = s;
    __syncthreads();
    for (int o = 1; o < 1024; o <<= 1) {
        int v = (t >= o) ? sh[t - o] : 0;
        __syncthreads();
        sh[t] += v;
        __syncthreads();
    }
    int ex = sh[t] - s;
    #pragma unroll
    for (int j = 0; j < CH; j++) {
        int idx = base + j;
        if (idx < N_ATOMS) { g_off[idx] = ex; ex += loc[j]; }
    }
    if (t == 1023) g_off[N_ATOMS] = sh[1023];
}

// ---------------- kernel 3: CSR fill ------------------------------------------
__global__ void k_fill(const int* __restrict__ rcv) {
    int e = blockIdx.x * blockDim.x + threadIdx.x;
    if (e >= N_EDGES) return;
    int r = rcv[e];
    int p = g_off[r] + atomicAdd(&g_fill[r], 1);
    g_csr[p] = e;
}

// ---------------- kernel 4: phase A gather (one block per atom) --------------
// b-axis-contiguous layouts: wr transposed to [k][b], T to [s][lm*8+b],
// E1 to [c][lm*8+b] so E1-build and the output contraction use LDS.128.
__global__ void __launch_bounds__(128) k_phaseA(
    const float* __restrict__ emb,
    const float* __restrict__ Wr0, const float* __restrict__ Wr1,
    const float* __restrict__ Wr2, const float* __restrict__ Wr3,
    const int* __restrict__ species) {
    __shared__ float4 wr4[640];       // 2560 floats, transposed [k][b]
    __shared__ float  em[64];
    __shared__ float4 T4[128];        // 512 floats: T[s][lm*8+b]
    __shared__ float4 E1_4[512];      // 2048 floats: E1[c][lm*8+b]
    __shared__ float  sg[16 * 24];
    __shared__ int    es[16];

    float* wr = (float*)wr4;
    float* T  = (float*)T4;

    int t = threadIdx.x;
    int i = blockIdx.x;

    // transposed weight load: wr[woff + k*8 + b] = Wr_l[b*Kl + k]
    for (int j = t; j < 1024; j += 128) {
        int b = j >> 7, k = j & 127;
        wr[(k << 3) + b] = Wr0[j];
    }
    for (int j = t; j < 768; j += 128) {
        int b = j / 96, k = j - b * 96;
        wr[1024 + k * 8 + b] = Wr1[j];
    }
    for (int j = t; j < 512; j += 128) {
        int b = j >> 6, k = j & 63;
        wr[1792 + (k << 3) + b] = Wr2[j];
    }
    for (int j = t; j < 256; j += 128) {
        int b = j >> 5, k = j & 31;
        wr[2304 + (k << 3) + b] = Wr3[j];
    }
    if (t < 64) em[t] = emb[t];

    int b = t >> 4, lm = t & 15;
    float a0 = 0.f, a1 = 0.f, a2 = 0.f, a3 = 0.f;
    int start = g_off[i];
    int deg = g_off[i + 1] - start;
    __syncthreads();

    for (int c0 = 0; c0 < deg; c0 += 16) {
        int nn = min(16, deg - c0);
        if (t < nn) es[t] = g_csr[start + c0 + t];
        __syncthreads();
        for (int j = t; j < nn * 24; j += 128) {
            int ec = j / 24, w = j - ec * 24;
            sg[ec * 24 + w] = g_geo[(size_t)es[ec] * 24 + w];
        }
        __syncthreads();
        for (int ec = 0; ec < nn; ec++) {
            float R  = sg[ec * 24 + b];
            float Yv = (lm == 0) ? 1.0f : sg[ec * 24 + 7 + lm];
            int sp = __float_as_int(sg[ec * 24 + 23]);
            float v = R * Yv;
            if      (sp == 0) a0 += v;
            else if (sp == 1) a1 += v;
            else if (sp == 2) a2 += v;
            else              a3 += v;
        }
        __syncthreads();
    }
    {
        int tl = (lm << 3) + b;        // transposed slot
        T[tl]        = a0;
        T[128 + tl]  = a1;
        T[256 + tl]  = a2;
        T[384 + tl]  = a3;
    }
    __syncthreads();

    // E1[c][lm*8+b] = sum_s em[s*16+c] * T[s][lm*8+b]   (float4 over b-axis)
    for (int j4 = t; j4 < 512; j4 += 128) {
        int c = j4 >> 5, r4 = j4 & 31;
        float4 t0 = T4[r4], t1 = T4[32 + r4], t2 = T4[64 + r4], t3 = T4[96 + r4];
        float e0 = em[c], e1 = em[16 + c], e2 = em[32 + c], e3 = em[48 + c];
        float4 o;
        o.x = e0 * t0.x + e1 * t1.x + e2 * t2.x + e3 * t3.x;
        o.y = e0 * t0.y + e1 * t1.y + e2 * t2.y + e3 * t3.y;
        o.z = e0 * t0.z + e1 * t1.z + e2 * t2.z + e3 * t3.z;
        o.w = e0 * t0.w + e1 * t1.w + e2 * t2.w + e3 * t3.w;
        E1_4[j4] = o;
    }
    __syncthreads();

    int spi = species[i];
    __half* out = g_Aemb + (size_t)i * FV;
    for (int kp = t; kp < FV; kp += 128) {
        int k, nmax, lmb, woff;
        if (kp < 128)      { k = kp;                          nmax = 8; lmb = 0;     woff = 0;    }
        else if (kp < 416) { int u = kp - 128; int m = u / 96; k = u - 96 * m; nmax = 6; lmb = 1 + m; woff = 1024; }
        else if (kp < 736) { int u = kp - 416; int m = u >> 6; k = u & 63;     nmax = 4; lmb = 4 + m; woff = 1792; }
        else               { int u = kp - 736; int m = u >> 5; k = u & 31;     nmax = 2; lmb = 9 + m; woff = 2304; }
        int c = k / nmax;
        const float4* e4 = &E1_4[(c << 5) + (lmb << 1)];           // c*128 + lmb*8 floats
        const float4* w4 = &wr4[(woff >> 2) + (k << 1)];           // woff + k*8 floats
        float4 ea = e4[0], eb = e4[1];
        float4 wa = w4[0], wb = w4[1];
        float v = ea.x * wa.x + ea.y * wa.y + ea.z * wa.z + ea.w * wa.w
                + eb.x * wb.x + eb.y * wb.y + eb.z * wb.z + eb.w * wb.w;
        out[kp] = __float2half(0.1f * em[spi * 16 + c] * v);
    }
}

// ---------------- kernel 5: phase B gather (one block per atom, 320 thr) -----
// Re staged as float4 pairs; inner loop reads 2x LDS.128 broadcast per edge
// instead of 8 scalar LDS. Tile 32 + unroll 4 preserved from the 420us config.
__global__ void __launch_bounds__(320) k_phaseB(
    const float* __restrict__ Vr0, const float* __restrict__ Vr1,
    const float* __restrict__ Vr2, const float* __restrict__ Vr3,
    const int* __restrict__ snd) {
    __shared__ int    se[32];
    __shared__ int    ee[32];
    __shared__ float4 Re4[32 * 2];
    __shared__ float  Bsh[FV];
    __shared__ float  invsh[192];

    int t = threadIdx.x;
    int i = blockIdx.x;

    int lvl, k, base;
    const float* Vp; int Kl;
    if (t < 128)      { lvl = 0; k = t;       base = k;       Vp = Vr0; Kl = 128; }
    else if (t < 224) { lvl = 1; k = t - 128; base = 128 + k; Vp = Vr1; Kl = 96;  }
    else if (t < 288) { lvl = 2; k = t - 224; base = 416 + k; Vp = Vr2; Kl = 64;  }
    else              { lvl = 3; k = t - 288; base = 736 + k; Vp = Vr3; Kl = 32;  }
    float v0 = Vp[0 * Kl + k], v1 = Vp[1 * Kl + k], v2 = Vp[2 * Kl + k], v3 = Vp[3 * Kl + k];
    float v4 = Vp[4 * Kl + k], v5 = Vp[5 * Kl + k], v6 = Vp[6 * Kl + k], v7 = Vp[7 * Kl + k];

    float a0 = 0.f, a1 = 0.f, a2 = 0.f, a3 = 0.f, a4 = 0.f, a5 = 0.f, a6 = 0.f;

    int start = g_off[i];
    int deg = g_off[i + 1] - start;

    for (int c0 = 0; c0 < deg; c0 += 32) {
        int nn = min(32, deg - c0);
        if (t < nn) {
            int e = g_csr[start + c0 + t];
            ee[t] = e;
            se[t] = snd[e];
        }
        __syncthreads();
        // stage R[8] per edge as two float4s (64 float4s total)
        for (int j = t; j < nn * 2; j += 320) {
            int ec = j >> 1, h = j & 1;
            Re4[(ec << 1) + h] = ((const float4*)(g_geo + (size_t)ee[ec] * 24))[h];
        }
        __syncthreads();

        if (lvl == 0) {
            #pragma unroll 4
            for (int ec = 0; ec < nn; ec++) {
                const __half* ar = g_Aemb + (size_t)se[ec] * FV;
                float4 ra = Re4[ec * 2], rb = Re4[ec * 2 + 1];
                float vl = ra.x*v0 + ra.y*v1 + ra.z*v2 + ra.w*v3
                         + rb.x*v4 + rb.y*v5 + rb.z*v6 + rb.w*v7;
                a0 += __half2float(ar[base]) * vl;
            }
        } else if (lvl == 1) {
            #pragma unroll 4
            for (int ec = 0; ec < nn; ec++) {
                const __half* ar = g_Aemb + (size_t)se[ec] * FV;
                float4 ra = Re4[ec * 2], rb = Re4[ec * 2 + 1];
                float vl = ra.x*v0 + ra.y*v1 + ra.z*v2 + ra.w*v3
                         + rb.x*v4 + rb.y*v5 + rb.z*v6 + rb.w*v7;
                a0 += __half2float(ar[base])       * vl;
                a1 += __half2float(ar[base + 96])  * vl;
                a2 += __half2float(ar[base + 192]) * vl;
            }
        } else if (lvl == 2) {
            #pragma unroll 4
            for (int ec = 0; ec < nn; ec++) {
                const __half* ar = g_Aemb + (size_t)se[ec] * FV;
                float4 ra = Re4[ec * 2], rb = Re4[ec * 2 + 1];
                float vl = ra.x*v0 + ra.y*v1 + ra.z*v2 + ra.w*v3
                         + rb.x*v4 + rb.y*v5 + rb.z*v6 + rb.w*v7;
                a0 += __half2float(ar[base])       * vl;
                a1 += __half2float(ar[base + 64])  * vl;
                a2 += __half2float(ar[base + 128]) * vl;
                a3 += __half2float(ar[base + 192]) * vl;
                a4 += __half2float(ar[base + 256]) * vl;
            }
        } else {
            #pragma unroll 4
            for (int ec = 0; ec < nn; ec++) {
                const __half* ar = g_Aemb + (size_t)se[ec] * FV;
                float4 ra = Re4[ec * 2], rb = Re4[ec * 2 + 1];
                float vl = ra.x*v0 + ra.y*v1 + ra.z*v2 + ra.w*v3
                         + rb.x*v4 + rb.y*v5 + rb.z*v6 + rb.w*v7;
                a0 += __half2float(ar[base])       * vl;
                a1 += __half2float(ar[base + 32])  * vl;
                a2 += __half2float(ar[base + 64])  * vl;
                a3 += __half2float(ar[base + 96])  * vl;
                a4 += __half2float(ar[base + 128]) * vl;
                a5 += __half2float(ar[base + 160]) * vl;
                a6 += __half2float(ar[base + 192]) * vl;
            }
        }
        __syncthreads();
    }

    if (lvl == 0) {
        Bsh[base] = 0.1f * a0;
    } else if (lvl == 1) {
        Bsh[base] = 0.1f * a0; Bsh[base + 96] = 0.1f * a1; Bsh[base + 192] = 0.1f * a2;
    } else if (lvl == 2) {
        Bsh[base] = 0.1f * a0; Bsh[base + 64] = 0.1f * a1; Bsh[base + 128] = 0.1f * a2;
        Bsh[base + 192] = 0.1f * a3; Bsh[base + 256] = 0.1f * a4;
    } else {
        Bsh[base] = 0.1f * a0; Bsh[base + 32] = 0.1f * a1; Bsh[base + 64] = 0.1f * a2;
        Bsh[base + 96] = 0.1f * a3; Bsh[base + 128] = 0.1f * a4;
        Bsh[base + 160] = 0.1f * a5; Bsh[base + 192] = 0.1f * a6;
    }
    __syncthreads();

    if (t < 192) {
        int off, KK, cnt, kk;
        float norm;
        if (t < 96)       { off = 128; KK = 96; cnt = 3; kk = t;       norm = 0.5773502691896258f; }
        else if (t < 160) { off = 416; KK = 64; cnt = 5; kk = t - 96;  norm = 0.4472135954999579f; }
        else              { off = 736; KK = 32; cnt = 7; kk = t - 160; norm = 0.3779644730092272f; }
        float s = 0.f;
        for (int m = 0; m < cnt; m++) { float v = Bsh[off + m * KK + kk]; s += v * v; }
        invsh[t] = s * norm;
    }
    __syncthreads();

    g_fpre[(size_t)i * FP + t] = (t < 128) ? Bsh[t] : invsh[t - 128];
}

// ---------------- kernel 6: tail (inv@N + MLP), 16 atoms / block -------------
__global__ void __launch_bounds__(256) k_tail(
    const float* __restrict__ N1, const float* __restrict__ N2,
    const float* __restrict__ N3,
    const float* __restrict__ W1, const float* __restrict__ W2,
    const float* __restrict__ w_out, const float* __restrict__ comp,
    const int* __restrict__ species) {
    __shared__ float fin[16 * FP];     // 20 KB
    __shared__ float f2sh[16 * 128];   // 8 KB (reused for stage-3 partials)
    __shared__ float h1sh[16 * 128];   // 8 KB

    int t = threadIdx.x;
    int blk = blockIdx.x;
    int c = t & 127;
    int g = t >> 7;
    int abase = g * 8;

    for (int j = t; j < 16 * FP; j += 256)
        fin[j] = g_fpre[(size_t)blk * 16 * FP + j];
    __syncthreads();

    float acc[8];
    #pragma unroll
    for (int a = 0; a < 8; a++) acc[a] = fin[(abase + a) * FP + c];
    for (int j = 0; j < 96; j++) {
        float nv = N1[j * 128 + c];
        #pragma unroll
        for (int a = 0; a < 8; a++) acc[a] += fin[(abase + a) * FP + 128 + j] * nv;
    }
    for (int j = 0; j < 64; j++) {
        float nv = N2[j * 128 + c];
        #pragma unroll
        for (int a = 0; a < 8; a++) acc[a] += fin[(abase + a) * FP + 224 + j] * nv;
    }
    for (int j = 0; j < 32; j++) {
        float nv = N3[j * 128 + c];
        #pragma unroll
        for (int a = 0; a < 8; a++) acc[a] += fin[(abase + a) * FP + 288 + j] * nv;
    }
    #pragma unroll
    for (int a = 0; a < 8; a++) f2sh[(abase + a) * 128 + c] = acc[a];
    __syncthreads();

    float acc2[8];
    #pragma unroll
    for (int a = 0; a < 8; a++) acc2[a] = 0.f;
    for (int kk = 0; kk < 128; kk++) {
        float w = W1[kk * 128 + c];
        #pragma unroll
        for (int a = 0; a < 8; a++) acc2[a] += f2sh[(abase + a) * 128 + kk] * w;
    }
    #pragma unroll
    for (int a = 0; a < 8; a++) {
        float s = acc2[a];
        h1sh[(abase + a) * 128 + c] = s / (1.0f + expf(-s));
    }
    __syncthreads();

    float acc3[8];
    #pragma unroll
    for (int a = 0; a < 8; a++) acc3[a] = 0.f;
    for (int kk = 0; kk < 128; kk++) {
        float w = W2[kk * 128 + c];
        #pragma unroll
        for (int a = 0; a < 8; a++) acc3[a] += h1sh[(abase + a) * 128 + kk] * w;
    }
    float wo = w_out[c];
    __syncthreads();
    #pragma unroll
    for (int a = 0; a < 8; a++) f2sh[(abase + a) * 128 + c] = acc3[a] * wo;
    __syncthreads();

    if (t < 16) {
        float s = 0.f;
        for (int j = 0; j < 128; j++) s += f2sh[t * 128 + j];
        int idx = blk * 16 + t;
        g_eatom[idx] = s + comp[species[idx]];
    }
}

// ---------------- kernel 7: final reduction + counter reset ------------------
__global__ void k_reduce(float* __restrict__ out) {
    __shared__ double sh[1024];
    int t = threadIdx.x;
    double s = 0.0;
    for (int i = t; i < N_ATOMS; i += 1024) s += (double)g_eatom[i];
    sh[t] = s;
    __syncthreads();
    for (int o = 512; o > 0; o >>= 1) {
        if (t < o) sh[t] += sh[t + o];
        __syncthreads();
    }
    if (t == 0) out[0] = (float)sh[0];
    for (int i = t; i < N_ATOMS; i += 1024) { g_deg[i] = 0; g_fill[i] = 0; }
}

// ---------------- launch ------------------------------------------------------
extern "C" void kernel_launch(void* const* d_in, const int* in_sizes, int n_in,
                              void* d_out, int out_size) {
    const float *pos = 0, *emb = 0, *Wr0 = 0, *Wr1 = 0, *Wr2 = 0, *Wr3 = 0;
    const float *Vr0 = 0, *Vr1 = 0, *Vr2 = 0, *Vr3 = 0;
    const float *N1 = 0, *N2 = 0, *N3 = 0, *W1 = 0, *W2 = 0, *w_out = 0, *comp = 0;
    const int *species = 0, *snd = 0, *rcv = 0;

    for (int i = 0; i < n_in; i++) {
        int s = in_sizes[i];
        const void* p = d_in[i];
        switch (s) {
            case 30000:  pos = (const float*)p; break;
            case 64:     emb = (const float*)p; break;
            case 10000:  species = (const int*)p; break;
            case 320000: if (!snd) snd = (const int*)p; else rcv = (const int*)p; break;
            case 1024:   if (!Wr0) Wr0 = (const float*)p; else Vr0 = (const float*)p; break;
            case 768:    if (!Wr1) Wr1 = (const float*)p; else Vr1 = (const float*)p; break;
            case 512:    if (!Wr2) Wr2 = (const float*)p; else Vr2 = (const float*)p; break;
            case 256:    if (!Wr3) Wr3 = (const float*)p; else Vr3 = (const float*)p; break;
            case 12288:  N1 = (const float*)p; break;  // M1 then N1: keep LAST
            case 8192:   N2 = (const float*)p; break;  // M2 then N2: keep LAST
            case 4096:   N3 = (const float*)p; break;  // M3 then N3: keep LAST
            case 16384:  if (!W1) W1 = (const float*)p; else W2 = (const float*)p; break;
            case 128:    w_out = (const float*)p; break;
            case 4:      comp = (const float*)p; break;
            default: break;
        }
    }

    float* out = (float*)d_out;

    k_geom<<<(N_EDGES + 255) / 256, 256>>>(pos, species, snd, rcv);
    k_scan<<<1, 1024>>>();
    k_fill<<<(N_EDGES + 255) / 256, 256>>>(rcv);
    k_phaseA<<<N_ATOMS, 128>>>(emb, Wr0, Wr1, Wr2, Wr3, species);
    k_phaseB<<<N_ATOMS, 320>>>(Vr0, Vr1, Vr2, Vr3, snd);
    k_tail<<<N_ATOMS / 16, 256>>>(N1, N2, N3, W1, W2, w_out, comp, species);
    k_reduce<<<1, 1024>>>(out);
}